// round 2
// baseline (speedup 1.0000x reference)
#include <cuda_runtime.h>
#include <math.h>

#define N_PTS 8192
#define C_DIM 256
#define KNN   16

// ---------------- scratch (device globals; no allocations allowed) ----------
__device__ int   g_idx[N_PTS * KNN];
__device__ float g_delta[N_PTS * KNN * 3];
__device__ float g_theta[N_PTS * C_DIM];
__device__ float g_phi[N_PTS * C_DIM];
__device__ float g_gf[N_PTS * C_DIM];
__device__ float g_pe[(size_t)N_PTS * KNN * C_DIM];   // 128 MB
__device__ float g_y[N_PTS * C_DIM];

// ---------------- KNN: 1 thread per query, smem-tiled candidates ------------
__global__ void knn_kernel(const float* __restrict__ coords) {
    const int TILE = 512;
    __shared__ float4 sc[TILE];
    int q = blockIdx.x * blockDim.x + threadIdx.x;   // exactly 8192 threads
    float qx = coords[q * 3 + 0], qy = coords[q * 3 + 1], qz = coords[q * 3 + 2];
    float qs = qx * qx + qy * qy + qz * qz;

    float bd[KNN];
    int   bi[KNN];
#pragma unroll
    for (int s = 0; s < KNN; s++) { bd[s] = 3.4e38f; bi[s] = -1; }

    for (int base = 0; base < N_PTS; base += TILE) {
        __syncthreads();
        for (int t = threadIdx.x; t < TILE; t += blockDim.x) {
            float x = coords[(base + t) * 3 + 0];
            float y = coords[(base + t) * 3 + 1];
            float z = coords[(base + t) * 3 + 2];
            sc[t] = make_float4(x, y, z, x * x + y * y + z * z);
        }
        __syncthreads();
        for (int t = 0; t < TILE; t++) {
            float4 cc = sc[t];
            float dot = qx * cc.x + qy * cc.y + qz * cc.z;
            float d2 = qs + cc.w - 2.0f * dot;
            if (d2 < bd[KNN - 1]) {
                float cd = d2; int ci = base + t;
#pragma unroll
                for (int s = 0; s < KNN; s++) {
                    if (cd < bd[s]) {
                        float td = bd[s]; int ti = bi[s];
                        bd[s] = cd; bi[s] = ci; cd = td; ci = ti;
                    }
                }
            }
        }
    }
#pragma unroll
    for (int s = 0; s < KNN; s++) {
        int j = bi[s];
        g_idx[q * KNN + s] = j;
        g_delta[(q * KNN + s) * 3 + 0] = coords[j * 3 + 0] - qx;
        g_delta[(q * KNN + s) * 3 + 1] = coords[j * 3 + 1] - qy;
        g_delta[(q * KNN + s) * 3 + 2] = coords[j * 3 + 2] - qz;
    }
}

// ---------------- fp32 tiled GEMM: C = A[M,K] @ B[K,N] + bias (+ resid) -----
#define BM 128
#define BN 64
#define BK 16
#define TM 8
#define TN 4

__global__ __launch_bounds__(256) void gemm_bias_kernel(
    const float* __restrict__ A, const float* __restrict__ B,
    const float* __restrict__ bias, const float* __restrict__ resid,
    float* __restrict__ Cout, int M, int Ncols, int Kd)
{
    __shared__ float As[BK][BM + 4];
    __shared__ float Bs[BK][BN];
    int m0 = blockIdx.y * BM;
    int n0 = blockIdx.x * BN;
    int tid = threadIdx.x;
    int tx = tid & 15, ty = tid >> 4;     // tx: N dir, ty: M dir
    float acc[TM][TN] = {};

    for (int k0 = 0; k0 < Kd; k0 += BK) {
        // A tile: 128x16 = 512 float4, 2 per thread, store transposed
#pragma unroll
        for (int l = tid; l < (BM * BK / 4); l += 256) {
            int row = l >> 2, c4 = (l & 3) * 4;
            float4 v = *(const float4*)(A + (size_t)(m0 + row) * Kd + k0 + c4);
            As[c4 + 0][row] = v.x; As[c4 + 1][row] = v.y;
            As[c4 + 2][row] = v.z; As[c4 + 3][row] = v.w;
        }
        // B tile: 16x64 = 256 float4, 1 per thread
        {
            int row = tid >> 4, c4 = (tid & 15) * 4;
            *(float4*)&Bs[row][c4] =
                *(const float4*)(B + (size_t)(k0 + row) * Ncols + n0 + c4);
        }
        __syncthreads();
#pragma unroll
        for (int kk = 0; kk < BK; kk++) {
            float a[TM], b[TN];
#pragma unroll
            for (int i = 0; i < TM; i++) a[i] = As[kk][ty * TM + i];
#pragma unroll
            for (int j = 0; j < TN; j++) b[j] = Bs[kk][tx * TN + j];
#pragma unroll
            for (int i = 0; i < TM; i++)
#pragma unroll
                for (int j = 0; j < TN; j++)
                    acc[i][j] = fmaf(a[i], b[j], acc[i][j]);
        }
        __syncthreads();
    }
#pragma unroll
    for (int i = 0; i < TM; i++) {
        int m = m0 + ty * TM + i;
#pragma unroll
        for (int j = 0; j < TN; j++) {
            int n = n0 + tx * TN + j;
            float v = acc[i][j] + bias[n];
            if (resid) v += resid[(size_t)m * Ncols + n];
            Cout[(size_t)m * Ncols + n] = v;
        }
    }
}

// ---------------- pe GEMM: A = relu(delta @ w1 + b1) generated on the fly ---
__global__ __launch_bounds__(256) void pe_gemm_kernel(
    const float* __restrict__ w1, const float* __restrict__ b1,
    const float* __restrict__ w2, const float* __restrict__ b2)
{
    __shared__ float As[BK][BM + 4];
    __shared__ float Bs[BK][BN];
    __shared__ float ds[BM][3];
    int m0 = blockIdx.y * BM;            // rows of N*K
    int n0 = blockIdx.x * BN;
    int tid = threadIdx.x;
    int tx = tid & 15, ty = tid >> 4;
    float acc[TM][TN] = {};

    for (int l = tid; l < BM * 3; l += 256)
        ds[l / 3][l % 3] = g_delta[(size_t)m0 * 3 + l];
    __syncthreads();

    for (int k0 = 0; k0 < C_DIM; k0 += BK) {
        // generate A tile: thread owns one hidden channel j = k0 + (tid&15)
        {
            int kk = tid & 15, rg = tid >> 4;
            int j = k0 + kk;
            float wa = w1[j], wb = w1[C_DIM + j], wc = w1[2 * C_DIM + j];
            float bb = b1[j];
#pragma unroll
            for (int i = 0; i < 8; i++) {
                int row = rg * 8 + i;
                float h = fmaf(ds[row][0], wa,
                          fmaf(ds[row][1], wb,
                          fmaf(ds[row][2], wc, bb)));
                As[kk][row] = fmaxf(h, 0.0f);
            }
        }
        // B tile from w2
        {
            int row = tid >> 4, c4 = (tid & 15) * 4;
            *(float4*)&Bs[row][c4] =
                *(const float4*)(w2 + (size_t)(k0 + row) * C_DIM + n0 + c4);
        }
        __syncthreads();
#pragma unroll
        for (int kk = 0; kk < BK; kk++) {
            float a[TM], b[TN];
#pragma unroll
            for (int i = 0; i < TM; i++) a[i] = As[kk][ty * TM + i];
#pragma unroll
            for (int j = 0; j < TN; j++) b[j] = Bs[kk][tx * TN + j];
#pragma unroll
            for (int i = 0; i < TM; i++)
#pragma unroll
                for (int j = 0; j < TN; j++)
                    acc[i][j] = fmaf(a[i], b[j], acc[i][j]);
        }
        __syncthreads();
    }
#pragma unroll
    for (int i = 0; i < TM; i++) {
        size_t m = m0 + ty * TM + i;
#pragma unroll
        for (int j = 0; j < TN; j++) {
            int n = n0 + tx * TN + j;
            g_pe[m * C_DIM + n] = acc[i][j] + b2[n];
        }
    }
}

// ---------------- softmax over K + weighted sum of g ------------------------
__global__ void attn_kernel() {
    int n = blockIdx.x;
    int c = threadIdx.x;                  // 256 threads = channels
    __shared__ int sidx[KNN];
    if (c < KNN) sidx[c] = g_idx[n * KNN + c];
    __syncthreads();

    float t = g_theta[n * C_DIM + c];
    float df[KNN];
    float m = -3.4e38f;
#pragma unroll
    for (int k = 0; k < KNN; k++) {
        int j = sidx[k];
        float ph = g_phi[(size_t)j * C_DIM + c];
        float pe = g_pe[((size_t)n * KNN + k) * C_DIM + c];
        float v = pe * (t - ph + 1.0f) * 0.0625f;   // /sqrt(256)
        df[k] = v;
        m = fmaxf(m, v);
    }
    float s = 0.0f;
#pragma unroll
    for (int k = 0; k < KNN; k++) { df[k] = __expf(df[k] - m); s += df[k]; }
    float inv = 1.0f / s;
    float y = 0.0f;
#pragma unroll
    for (int k = 0; k < KNN; k++) {
        int j = sidx[k];
        y = fmaf(df[k] * inv, g_gf[(size_t)j * C_DIM + c], y);
    }
    g_y[n * C_DIM + c] = y;
}

// ---------------- launch ----------------------------------------------------
extern "C" void kernel_launch(void* const* d_in, const int* in_sizes, int n_in,
                              void* d_out, int out_size) {
    const float* coords  = (const float*)d_in[0];
    const float* feats   = (const float*)d_in[1];
    const float* theta_w = (const float*)d_in[2];
    const float* theta_b = (const float*)d_in[3];
    const float* phi_w   = (const float*)d_in[4];
    const float* phi_b   = (const float*)d_in[5];
    const float* g_w     = (const float*)d_in[6];
    const float* g_b     = (const float*)d_in[7];
    const float* pe1_w1  = (const float*)d_in[8];
    const float* pe1_b1  = (const float*)d_in[9];
    const float* pe1_w2  = (const float*)d_in[10];
    const float* pe1_b2  = (const float*)d_in[11];
    const float* W_w     = (const float*)d_in[12];
    const float* W_b     = (const float*)d_in[13];
    float* out = (float*)d_out;

    float *p_theta, *p_phi, *p_gf, *p_y;
    cudaGetSymbolAddress((void**)&p_theta, g_theta);
    cudaGetSymbolAddress((void**)&p_phi,   g_phi);
    cudaGetSymbolAddress((void**)&p_gf,    g_gf);
    cudaGetSymbolAddress((void**)&p_y,     g_y);

    knn_kernel<<<N_PTS / 256, 256>>>(coords);

    dim3 g1(C_DIM / BN, N_PTS / BM);   // (4, 64)
    gemm_bias_kernel<<<g1, 256>>>(feats, theta_w, theta_b, nullptr, p_theta,
                                  N_PTS, C_DIM, C_DIM);
    gemm_bias_kernel<<<g1, 256>>>(feats, phi_w, phi_b, nullptr, p_phi,
                                  N_PTS, C_DIM, C_DIM);
    gemm_bias_kernel<<<g1, 256>>>(feats, g_w, g_b, nullptr, p_gf,
                                  N_PTS, C_DIM, C_DIM);

    dim3 g2(C_DIM / BN, N_PTS * KNN / BM);  // (4, 1024)
    pe_gemm_kernel<<<g2, 256>>>(pe1_w1, pe1_b1, pe1_w2, pe1_b2);

    attn_kernel<<<N_PTS, 256>>>();

    gemm_bias_kernel<<<g1, 256>>>(p_y, W_w, W_b, feats, out,
                                  N_PTS, C_DIM, C_DIM);
}

// round 3
// speedup vs baseline: 1.3812x; 1.3812x over previous
#include <cuda_runtime.h>
#include <cuda_bf16.h>
#include <math.h>
#include <stdint.h>

#define N_PTS 8192
#define C_DIM 256
#define KNN   16

// ---------------- scratch (device globals; no allocations allowed) ----------
__device__ int   g_idx[N_PTS * KNN];
__device__ float g_delta[N_PTS * KNN * 3];
__device__ float g_theta[N_PTS * C_DIM];
__device__ float g_phi[N_PTS * C_DIM];
__device__ float g_gf[N_PTS * C_DIM];
__device__ float g_y[N_PTS * C_DIM];
__device__ __nv_bfloat16 g_w2t[C_DIM * C_DIM];   // w2 transposed, bf16: [n][k]

// ---------------- KNN: 1 thread per query, smem-tiled candidates ------------
__global__ void knn_kernel(const float* __restrict__ coords) {
    const int TILE = 512;
    __shared__ float4 sc[TILE];
    int q = blockIdx.x * blockDim.x + threadIdx.x;   // exactly 8192 threads
    float qx = coords[q * 3 + 0], qy = coords[q * 3 + 1], qz = coords[q * 3 + 2];
    float qs = qx * qx + qy * qy + qz * qz;

    float bd[KNN];
    int   bi[KNN];
#pragma unroll
    for (int s = 0; s < KNN; s++) { bd[s] = 3.4e38f; bi[s] = -1; }

    for (int base = 0; base < N_PTS; base += TILE) {
        __syncthreads();
        for (int t = threadIdx.x; t < TILE; t += blockDim.x) {
            float x = coords[(base + t) * 3 + 0];
            float y = coords[(base + t) * 3 + 1];
            float z = coords[(base + t) * 3 + 2];
            sc[t] = make_float4(x, y, z, x * x + y * y + z * z);
        }
        __syncthreads();
        for (int t = 0; t < TILE; t++) {
            float4 cc = sc[t];
            float dot = qx * cc.x + qy * cc.y + qz * cc.z;
            float d2 = qs + cc.w - 2.0f * dot;
            if (d2 < bd[KNN - 1]) {
                float cd = d2; int ci = base + t;
#pragma unroll
                for (int s = 0; s < KNN; s++) {
                    if (cd < bd[s]) {
                        float td = bd[s]; int ti = bi[s];
                        bd[s] = cd; bi[s] = ci; cd = td; ci = ti;
                    }
                }
            }
        }
    }
#pragma unroll
    for (int s = 0; s < KNN; s++) {
        int j = bi[s];
        g_idx[q * KNN + s] = j;
        g_delta[(q * KNN + s) * 3 + 0] = coords[j * 3 + 0] - qx;
        g_delta[(q * KNN + s) * 3 + 1] = coords[j * 3 + 1] - qy;
        g_delta[(q * KNN + s) * 3 + 2] = coords[j * 3 + 2] - qz;
    }
}

// ---------------- fp32 tiled GEMM: C = A[M,K] @ B[K,N] + bias (+ resid) -----
#define BM 128
#define BN 64
#define BK 16
#define TM 8
#define TN 4

__global__ __launch_bounds__(256) void gemm_bias_kernel(
    const float* __restrict__ A, const float* __restrict__ B,
    const float* __restrict__ bias, const float* __restrict__ resid,
    float* __restrict__ Cout, int M, int Ncols, int Kd)
{
    __shared__ float As[BK][BM + 4];
    __shared__ float Bs[BK][BN];
    int m0 = blockIdx.y * BM;
    int n0 = blockIdx.x * BN;
    int tid = threadIdx.x;
    int tx = tid & 15, ty = tid >> 4;     // tx: N dir, ty: M dir
    float acc[TM][TN] = {};

    for (int k0 = 0; k0 < Kd; k0 += BK) {
#pragma unroll
        for (int l = tid; l < (BM * BK / 4); l += 256) {
            int row = l >> 2, c4 = (l & 3) * 4;
            float4 v = *(const float4*)(A + (size_t)(m0 + row) * Kd + k0 + c4);
            As[c4 + 0][row] = v.x; As[c4 + 1][row] = v.y;
            As[c4 + 2][row] = v.z; As[c4 + 3][row] = v.w;
        }
        {
            int row = tid >> 4, c4 = (tid & 15) * 4;
            *(float4*)&Bs[row][c4] =
                *(const float4*)(B + (size_t)(k0 + row) * Ncols + n0 + c4);
        }
        __syncthreads();
#pragma unroll
        for (int kk = 0; kk < BK; kk++) {
            float a[TM], b[TN];
#pragma unroll
            for (int i = 0; i < TM; i++) a[i] = As[kk][ty * TM + i];
#pragma unroll
            for (int j = 0; j < TN; j++) b[j] = Bs[kk][tx * TN + j];
#pragma unroll
            for (int i = 0; i < TM; i++)
#pragma unroll
                for (int j = 0; j < TN; j++)
                    acc[i][j] = fmaf(a[i], b[j], acc[i][j]);
        }
        __syncthreads();
    }
#pragma unroll
    for (int i = 0; i < TM; i++) {
        int m = m0 + ty * TM + i;
#pragma unroll
        for (int j = 0; j < TN; j++) {
            int n = n0 + tx * TN + j;
            float v = acc[i][j] + bias[n];
            if (resid) v += resid[(size_t)m * Ncols + n];
            Cout[(size_t)m * Ncols + n] = v;
        }
    }
}

// ---------------- prep: w2 -> bf16 transposed --------------------------------
__global__ void w2_prep_kernel(const float* __restrict__ w2) {
    int t = blockIdx.x * blockDim.x + threadIdx.x;   // 65536 threads
    int n = t >> 8, k = t & 255;
    g_w2t[n * C_DIM + k] = __float2bfloat16(w2[k * C_DIM + n]);
}

// ---------------- fused pe GEMM (bf16 HMMA) + softmax attention -------------
// Tile: 128 rows (8 points x 16 neighbors) x 64 channels, K = 256 hidden.
// A = relu(delta @ w1 + b1) generated on the fly as bf16, B = w2^T bf16.
// Epilogue: softmax over the 16 neighbor rows per (point, channel), gather
// phi/g from L2-resident tables, write y directly (g_pe never materialized).
#define PAD_A 40     // bf16 row stride for As (80 B, 16B-aligned)
#define PAD_B 40     // bf16 row stride for Bs
#define PAD_C 68     // fp32 row stride for Cs

__global__ __launch_bounds__(256) void pe_attn_kernel(
    const float* __restrict__ w1, const float* __restrict__ b1,
    const float* __restrict__ b2)
{
    // union region: mainloop tiles vs epilogue accumulator tile
    __shared__ __align__(16) char smem_buf[128 * PAD_C * 4];  // 34816 B
    __nv_bfloat16 (*As)[PAD_A] = (__nv_bfloat16 (*)[PAD_A])smem_buf;           // 128x40 bf16
    __nv_bfloat16 (*Bs)[PAD_B] = (__nv_bfloat16 (*)[PAD_B])(smem_buf + 128 * PAD_A * 2); // 64x40
    float (*Cs)[PAD_C] = (float (*)[PAD_C])smem_buf;                            // 128x68 f32

    __shared__ float ds[128][3];
    __shared__ float b2s[64];
    __shared__ int   idxs[128];

    const int tid  = threadIdx.x;
    const int lane = tid & 31;
    const int wid  = tid >> 5;
    const int warp_m = wid & 3;          // 4 row-blocks of 32
    const int warp_n = wid >> 2;         // 2 col-blocks of 32
    const int qg = lane & 3;             // thread-in-group
    const int gr = lane >> 2;            // group id (row/col within 8)

    const int m0  = blockIdx.y * 128;    // row offset into N*K
    const int n0  = blockIdx.x * 64;     // channel offset
    const int pt0 = blockIdx.y * 8;      // first point of this tile

    // preload per-tile constants
    for (int l = tid; l < 384; l += 256) ds[l / 3][l % 3] = g_delta[(size_t)m0 * 3 + l];
    if (tid < 64)  b2s[tid] = b2[n0 + tid];
    if (tid < 128) idxs[tid] = g_idx[pt0 * KNN + tid];

    float acc[2][4][4] = {};

    const __nv_bfloat16* w2t = g_w2t;
    const int jcol = tid & 31;           // hidden channel within chunk (A-gen)
    const int rgrp = tid >> 5;           // row group (16 rows) for A-gen
    const int bn   = tid >> 2;           // B-load row (0..63)
    const int bseg = tid & 3;            // B-load 16B segment

    for (int k0 = 0; k0 < C_DIM; k0 += 32) {
        __syncthreads();   // protect As/Bs from previous iteration readers
        // ---- generate A tile: h = relu(delta @ w1 + b1), bf16 ----
        {
            int jg = k0 + jcol;
            float wa = w1[jg], wb = w1[C_DIM + jg], wc = w1[2 * C_DIM + jg];
            float bb = b1[jg];
#pragma unroll
            for (int i = 0; i < 16; i++) {
                int r = rgrp * 16 + i;
                float h = fmaf(ds[r][0], wa, fmaf(ds[r][1], wb, fmaf(ds[r][2], wc, bb)));
                As[r][jcol] = __float2bfloat16(fmaxf(h, 0.0f));
            }
        }
        // ---- load B tile: w2t rows n0..n0+63, cols k0..k0+31 ----
        {
            const uint4* src = (const uint4*)(w2t + (size_t)(n0 + bn) * C_DIM + k0 + bseg * 8);
            *(uint4*)&Bs[bn][bseg * 8] = *src;
        }
        __syncthreads();
        // ---- MMA: 2 k16 steps ----
#pragma unroll
        for (int kk = 0; kk < 32; kk += 16) {
            uint32_t a[2][4];
#pragma unroll
            for (int mt = 0; mt < 2; mt++) {
                int r = warp_m * 32 + mt * 16 + gr;
                a[mt][0] = *(const uint32_t*)&As[r    ][kk + 2 * qg];
                a[mt][1] = *(const uint32_t*)&As[r + 8][kk + 2 * qg];
                a[mt][2] = *(const uint32_t*)&As[r    ][kk + 2 * qg + 8];
                a[mt][3] = *(const uint32_t*)&As[r + 8][kk + 2 * qg + 8];
            }
#pragma unroll
            for (int nt = 0; nt < 4; nt++) {
                int nn = warp_n * 32 + nt * 8 + gr;
                uint32_t b0 = *(const uint32_t*)&Bs[nn][kk + 2 * qg];
                uint32_t b1r = *(const uint32_t*)&Bs[nn][kk + 2 * qg + 8];
#pragma unroll
                for (int mt = 0; mt < 2; mt++) {
                    asm volatile(
                        "mma.sync.aligned.m16n8k16.row.col.f32.bf16.bf16.f32 "
                        "{%0,%1,%2,%3}, {%4,%5,%6,%7}, {%8,%9}, {%0,%1,%2,%3};"
                        : "+f"(acc[mt][nt][0]), "+f"(acc[mt][nt][1]),
                          "+f"(acc[mt][nt][2]), "+f"(acc[mt][nt][3])
                        : "r"(a[mt][0]), "r"(a[mt][1]), "r"(a[mt][2]), "r"(a[mt][3]),
                          "r"(b0), "r"(b1r));
                }
            }
        }
    }
    __syncthreads();   // all warps done reading As/Bs; reuse region as Cs

    // ---- dump accumulators to Cs ----
#pragma unroll
    for (int mt = 0; mt < 2; mt++) {
#pragma unroll
        for (int nt = 0; nt < 4; nt++) {
            int r = warp_m * 32 + mt * 16 + gr;
            int c = warp_n * 32 + nt * 8 + 2 * qg;
            Cs[r    ][c    ] = acc[mt][nt][0];
            Cs[r    ][c + 1] = acc[mt][nt][1];
            Cs[r + 8][c    ] = acc[mt][nt][2];
            Cs[r + 8][c + 1] = acc[mt][nt][3];
        }
    }
    __syncthreads();

    // ---- fused softmax over K + weighted g sum ----
    // 8 points x 64 channels = 512 tasks; each thread does 2 channels.
    {
        int p  = tid >> 5;                 // point within tile
        int c0 = (tid & 31) * 2;
        int n_pt = pt0 + p;
        float tval0 = g_theta[(size_t)n_pt * C_DIM + n0 + c0];
        float tval1 = g_theta[(size_t)n_pt * C_DIM + n0 + c0 + 1];

#pragma unroll
        for (int cc = 0; cc < 2; cc++) {
            int c = c0 + cc;
            int cg = n0 + c;
            float tv = cc ? tval1 : tval0;
            float bb = b2s[c];
            float df[KNN];
            float mx = -3.4e38f;
#pragma unroll
            for (int k = 0; k < KNN; k++) {
                int j = idxs[p * KNN + k];
                float ph = g_phi[(size_t)j * C_DIM + cg];
                float pe = Cs[p * KNN + k][c] + bb;
                float v = pe * (tv - ph + 1.0f) * 0.0625f;
                df[k] = v;
                mx = fmaxf(mx, v);
            }
            float s = 0.0f;
#pragma unroll
            for (int k = 0; k < KNN; k++) { df[k] = __expf(df[k] - mx); s += df[k]; }
            float inv = 1.0f / s;
            float y = 0.0f;
#pragma unroll
            for (int k = 0; k < KNN; k++) {
                int j = idxs[p * KNN + k];
                y = fmaf(df[k] * inv, g_gf[(size_t)j * C_DIM + cg], y);
            }
            g_y[(size_t)n_pt * C_DIM + cg] = y;
        }
    }
}

// ---------------- launch ----------------------------------------------------
extern "C" void kernel_launch(void* const* d_in, const int* in_sizes, int n_in,
                              void* d_out, int out_size) {
    const float* coords  = (const float*)d_in[0];
    const float* feats   = (const float*)d_in[1];
    const float* theta_w = (const float*)d_in[2];
    const float* theta_b = (const float*)d_in[3];
    const float* phi_w   = (const float*)d_in[4];
    const float* phi_b   = (const float*)d_in[5];
    const float* g_w     = (const float*)d_in[6];
    const float* g_b     = (const float*)d_in[7];
    const float* pe1_w1  = (const float*)d_in[8];
    const float* pe1_b1  = (const float*)d_in[9];
    const float* pe1_w2  = (const float*)d_in[10];
    const float* pe1_b2  = (const float*)d_in[11];
    const float* W_w     = (const float*)d_in[12];
    const float* W_b     = (const float*)d_in[13];
    float* out = (float*)d_out;

    float *p_theta, *p_phi, *p_gf, *p_y;
    cudaGetSymbolAddress((void**)&p_theta, g_theta);
    cudaGetSymbolAddress((void**)&p_phi,   g_phi);
    cudaGetSymbolAddress((void**)&p_gf,    g_gf);
    cudaGetSymbolAddress((void**)&p_y,     g_y);

    knn_kernel<<<N_PTS / 256, 256>>>(coords);
    w2_prep_kernel<<<C_DIM * C_DIM / 256, 256>>>(pe1_w2);

    dim3 g1(C_DIM / BN, N_PTS / BM);   // (4, 64)
    gemm_bias_kernel<<<g1, 256>>>(feats, theta_w, theta_b, nullptr, p_theta,
                                  N_PTS, C_DIM, C_DIM);
    gemm_bias_kernel<<<g1, 256>>>(feats, phi_w, phi_b, nullptr, p_phi,
                                  N_PTS, C_DIM, C_DIM);
    gemm_bias_kernel<<<g1, 256>>>(feats, g_w, g_b, nullptr, p_gf,
                                  N_PTS, C_DIM, C_DIM);

    dim3 g2(C_DIM / 64, N_PTS * KNN / 128);  // (4, 1024)
    pe_attn_kernel<<<g2, 256>>>(pe1_w1, pe1_b1, pe1_b2);

    gemm_bias_kernel<<<g1, 256>>>(p_y, W_w, W_b, feats, out,
                                  N_PTS, C_DIM, C_DIM);
}

// round 4
// speedup vs baseline: 2.1549x; 1.5601x over previous
#include <cuda_runtime.h>
#include <cuda_bf16.h>
#include <math.h>
#include <stdint.h>

#define N_PTS 8192
#define C_DIM 256
#define KNN   16

// ---------------- scratch (device globals; no allocations allowed) ----------
__device__ int   g_idx[N_PTS * KNN];
__device__ float g_delta[N_PTS * KNN * 3];
__device__ float g_theta[N_PTS * C_DIM];
__device__ float g_phi[N_PTS * C_DIM];
__device__ float g_gf[N_PTS * C_DIM];
__device__ float g_y[N_PTS * C_DIM];
__device__ __nv_bfloat16 g_w2t[C_DIM * C_DIM];   // w2 transposed, bf16: [n][k]

// ---------------- KNN v2: 8 threads/query, private top-16 + 8-way merge -----
#define KTILE 512
#define QPB   32     // queries per block
#define TPQ   8      // threads per query

__global__ __launch_bounds__(256) void knn_kernel2(const float* __restrict__ coords) {
    __shared__ float4 sc[KTILE];               // 8 KB candidate tile
    __shared__ float  md[QPB][TPQ][KNN];       // 16 KB merge dists
    __shared__ int    mi[QPB][TPQ][KNN];       // 16 KB merge idx

    const int tid = threadIdx.x;
    const int ql  = tid >> 3;      // query within block
    const int g   = tid & 7;       // sub-scanner
    const int q   = blockIdx.x * QPB + ql;

    const float qx = coords[q * 3 + 0], qy = coords[q * 3 + 1], qz = coords[q * 3 + 2];
    const float qs = qx * qx + qy * qy + qz * qz;

    float bd[KNN];
    int   bi[KNN];
#pragma unroll
    for (int s = 0; s < KNN; s++) { bd[s] = 3.4e38f; bi[s] = 0x7fffffff; }

    for (int base = 0; base < N_PTS; base += KTILE) {
        __syncthreads();
        for (int t = tid; t < KTILE; t += 256) {
            float x = coords[(base + t) * 3 + 0];
            float y = coords[(base + t) * 3 + 1];
            float z = coords[(base + t) * 3 + 2];
            sc[t] = make_float4(x, y, z, x * x + y * y + z * z);
        }
        __syncthreads();
        const int t0 = g * (KTILE / TPQ);
#pragma unroll 4
        for (int tt = 0; tt < KTILE / TPQ; tt++) {
            float4 cc = sc[t0 + tt];
            float dot = qx * cc.x + qy * cc.y + qz * cc.z;
            float d2 = qs + cc.w - 2.0f * dot;
            if (d2 < bd[KNN - 1]) {
                float cd = d2; int ci = base + t0 + tt;
#pragma unroll
                for (int s = 0; s < KNN; s++) {
                    if (cd < bd[s]) {
                        float td = bd[s]; int ti = bi[s];
                        bd[s] = cd; bi[s] = ci; cd = td; ci = ti;
                    }
                }
            }
        }
    }
#pragma unroll
    for (int s = 0; s < KNN; s++) { md[ql][g][s] = bd[s]; mi[ql][g][s] = bi[s]; }
    __syncthreads();

    if (g == 0) {
        int h[TPQ] = {};
        for (int s = 0; s < KNN; s++) {
            float bdv = 3.4e38f; int biv = 0x7fffffff; int bl = 0;
#pragma unroll
            for (int l = 0; l < TPQ; l++) {
                float d = md[ql][l][h[l]];
                int   i = mi[ql][l][h[l]];
                if (d < bdv || (d == bdv && i < biv)) { bdv = d; biv = i; bl = l; }
            }
            h[bl]++;
            g_idx[q * KNN + s] = biv;
            g_delta[(q * KNN + s) * 3 + 0] = coords[biv * 3 + 0] - qx;
            g_delta[(q * KNN + s) * 3 + 1] = coords[biv * 3 + 1] - qy;
            g_delta[(q * KNN + s) * 3 + 2] = coords[biv * 3 + 2] - qz;
        }
    }
}

// ---------------- fp32 tiled GEMM (kept for final W layer, precision) -------
#define BM 128
#define BN 64
#define BK 16
#define TM 8
#define TN 4

__global__ __launch_bounds__(256) void gemm_bias_kernel(
    const float* __restrict__ A, const float* __restrict__ B,
    const float* __restrict__ bias, const float* __restrict__ resid,
    float* __restrict__ Cout, int M, int Ncols, int Kd)
{
    __shared__ float As[BK][BM + 4];
    __shared__ float Bs[BK][BN];
    int m0 = blockIdx.y * BM;
    int n0 = blockIdx.x * BN;
    int tid = threadIdx.x;
    int tx = tid & 15, ty = tid >> 4;
    float acc[TM][TN] = {};

    for (int k0 = 0; k0 < Kd; k0 += BK) {
#pragma unroll
        for (int l = tid; l < (BM * BK / 4); l += 256) {
            int row = l >> 2, c4 = (l & 3) * 4;
            float4 v = *(const float4*)(A + (size_t)(m0 + row) * Kd + k0 + c4);
            As[c4 + 0][row] = v.x; As[c4 + 1][row] = v.y;
            As[c4 + 2][row] = v.z; As[c4 + 3][row] = v.w;
        }
        {
            int row = tid >> 4, c4 = (tid & 15) * 4;
            *(float4*)&Bs[row][c4] =
                *(const float4*)(B + (size_t)(k0 + row) * Ncols + n0 + c4);
        }
        __syncthreads();
#pragma unroll
        for (int kk = 0; kk < BK; kk++) {
            float a[TM], b[TN];
#pragma unroll
            for (int i = 0; i < TM; i++) a[i] = As[kk][ty * TM + i];
#pragma unroll
            for (int j = 0; j < TN; j++) b[j] = Bs[kk][tx * TN + j];
#pragma unroll
            for (int i = 0; i < TM; i++)
#pragma unroll
                for (int j = 0; j < TN; j++)
                    acc[i][j] = fmaf(a[i], b[j], acc[i][j]);
        }
        __syncthreads();
    }
#pragma unroll
    for (int i = 0; i < TM; i++) {
        int m = m0 + ty * TM + i;
#pragma unroll
        for (int j = 0; j < TN; j++) {
            int n = n0 + tx * TN + j;
            float v = acc[i][j] + bias[n];
            if (resid) v += resid[(size_t)m * Ncols + n];
            Cout[(size_t)m * Ncols + n] = v;
        }
    }
}

// ---------------- tf32 tensor-core GEMM: C = A[8192,256]@B[256,256]+bias ----
__device__ __forceinline__ float to_tf32(float x) {
    float r;
    asm("cvt.rna.tf32.f32 %0, %1;" : "=f"(r) : "f"(x));
    return r;
}

#define TA_PAD 36   // As word stride
#define TB_PAD 72   // Bs word stride (72%32==8 -> conflict-free frag reads)

__global__ __launch_bounds__(256) void gemm_tf32_kernel(
    const float* __restrict__ A, const float* __restrict__ B,
    const float* __restrict__ bias, float* __restrict__ Cout)
{
    __shared__ float As[128][TA_PAD];   // 18 KB
    __shared__ float Bs[32][TB_PAD];    // 9 KB

    const int tid  = threadIdx.x;
    const int lane = tid & 31;
    const int wid  = tid >> 5;
    const int warp_m = wid & 3;      // 4 x 32 rows
    const int warp_n = wid >> 2;     // 2 x 32 cols
    const int qg = lane & 3;
    const int gr = lane >> 2;

    const int m0 = blockIdx.y * 128;
    const int n0 = blockIdx.x * 64;

    float acc[2][4][4] = {};

    const int ar  = tid >> 1, aseg = tid & 1;   // A: 2 threads/row, 16 floats each
    const int br  = tid >> 3, bseg = tid & 7;   // B: 8 threads/row, 8 floats each

    for (int k0 = 0; k0 < C_DIM; k0 += 32) {
        __syncthreads();
        {
            const float4* src = (const float4*)(A + (size_t)(m0 + ar) * C_DIM + k0 + aseg * 16);
#pragma unroll
            for (int i = 0; i < 4; i++) {
                float4 v = src[i];
                int c = aseg * 16 + i * 4;
                As[ar][c + 0] = to_tf32(v.x); As[ar][c + 1] = to_tf32(v.y);
                As[ar][c + 2] = to_tf32(v.z); As[ar][c + 3] = to_tf32(v.w);
            }
        }
        {
            const float4* src = (const float4*)(B + (size_t)(k0 + br) * C_DIM + n0 + bseg * 8);
            float4 v0 = src[0], v1 = src[1];
            int c = bseg * 8;
            Bs[br][c + 0] = to_tf32(v0.x); Bs[br][c + 1] = to_tf32(v0.y);
            Bs[br][c + 2] = to_tf32(v0.z); Bs[br][c + 3] = to_tf32(v0.w);
            Bs[br][c + 4] = to_tf32(v1.x); Bs[br][c + 5] = to_tf32(v1.y);
            Bs[br][c + 6] = to_tf32(v1.z); Bs[br][c + 7] = to_tf32(v1.w);
        }
        __syncthreads();
#pragma unroll
        for (int kk = 0; kk < 32; kk += 8) {
            uint32_t a[2][4];
#pragma unroll
            for (int mt = 0; mt < 2; mt++) {
                int r = warp_m * 32 + mt * 16 + gr;
                a[mt][0] = __float_as_uint(As[r    ][kk + qg]);
                a[mt][1] = __float_as_uint(As[r + 8][kk + qg]);
                a[mt][2] = __float_as_uint(As[r    ][kk + qg + 4]);
                a[mt][3] = __float_as_uint(As[r + 8][kk + qg + 4]);
            }
#pragma unroll
            for (int nt = 0; nt < 4; nt++) {
                int n = warp_n * 32 + nt * 8 + gr;
                uint32_t b0 = __float_as_uint(Bs[kk + qg    ][n]);
                uint32_t b1 = __float_as_uint(Bs[kk + qg + 4][n]);
#pragma unroll
                for (int mt = 0; mt < 2; mt++) {
                    asm volatile(
                        "mma.sync.aligned.m16n8k8.row.col.f32.tf32.tf32.f32 "
                        "{%0,%1,%2,%3}, {%4,%5,%6,%7}, {%8,%9}, {%0,%1,%2,%3};"
                        : "+f"(acc[mt][nt][0]), "+f"(acc[mt][nt][1]),
                          "+f"(acc[mt][nt][2]), "+f"(acc[mt][nt][3])
                        : "r"(a[mt][0]), "r"(a[mt][1]), "r"(a[mt][2]), "r"(a[mt][3]),
                          "r"(b0), "r"(b1));
                }
            }
        }
    }
#pragma unroll
    for (int mt = 0; mt < 2; mt++) {
#pragma unroll
        for (int nt = 0; nt < 4; nt++) {
            int r = warp_m * 32 + mt * 16 + gr;
            int c = warp_n * 32 + nt * 8 + 2 * qg;
            int n = n0 + c;
            float bn0 = bias[n], bn1 = bias[n + 1];
            float2 v0 = make_float2(acc[mt][nt][0] + bn0, acc[mt][nt][1] + bn1);
            float2 v1 = make_float2(acc[mt][nt][2] + bn0, acc[mt][nt][3] + bn1);
            *(float2*)(Cout + (size_t)(m0 + r    ) * C_DIM + n) = v0;
            *(float2*)(Cout + (size_t)(m0 + r + 8) * C_DIM + n) = v1;
        }
    }
}

// ---------------- prep: w2 -> bf16 transposed --------------------------------
__global__ void w2_prep_kernel(const float* __restrict__ w2) {
    int t = blockIdx.x * blockDim.x + threadIdx.x;   // 65536 threads
    int n = t >> 8, k = t & 255;
    g_w2t[n * C_DIM + k] = __float2bfloat16(w2[k * C_DIM + n]);
}

// ---------------- fused pe GEMM (bf16 HMMA) + softmax attention -------------
#define PAD_A 40
#define PAD_B 40
#define PAD_C 68

__global__ __launch_bounds__(256) void pe_attn_kernel(
    const float* __restrict__ w1, const float* __restrict__ b1,
    const float* __restrict__ b2)
{
    __shared__ __align__(16) char smem_buf[128 * PAD_C * 4];
    __nv_bfloat16 (*As)[PAD_A] = (__nv_bfloat16 (*)[PAD_A])smem_buf;
    __nv_bfloat16 (*Bs)[PAD_B] = (__nv_bfloat16 (*)[PAD_B])(smem_buf + 128 * PAD_A * 2);
    float (*Cs)[PAD_C] = (float (*)[PAD_C])smem_buf;

    __shared__ float ds[128][3];
    __shared__ float b2s[64];
    __shared__ int   idxs[128];

    const int tid  = threadIdx.x;
    const int lane = tid & 31;
    const int wid  = tid >> 5;
    const int warp_m = wid & 3;
    const int warp_n = wid >> 2;
    const int qg = lane & 3;
    const int gr = lane >> 2;

    const int m0  = blockIdx.y * 128;
    const int n0  = blockIdx.x * 64;
    const int pt0 = blockIdx.y * 8;

    for (int l = tid; l < 384; l += 256) ds[l / 3][l % 3] = g_delta[(size_t)m0 * 3 + l];
    if (tid < 64)  b2s[tid] = b2[n0 + tid];
    if (tid < 128) idxs[tid] = g_idx[pt0 * KNN + tid];

    float acc[2][4][4] = {};

    const __nv_bfloat16* w2t = g_w2t;
    const int jcol = tid & 31;
    const int rgrp = tid >> 5;
    const int bn   = tid >> 2;
    const int bseg = tid & 3;

    for (int k0 = 0; k0 < C_DIM; k0 += 32) {
        __syncthreads();
        {
            int jg = k0 + jcol;
            float wa = w1[jg], wb = w1[C_DIM + jg], wc = w1[2 * C_DIM + jg];
            float bb = b1[jg];
#pragma unroll
            for (int i = 0; i < 16; i++) {
                int r = rgrp * 16 + i;
                float h = fmaf(ds[r][0], wa, fmaf(ds[r][1], wb, fmaf(ds[r][2], wc, bb)));
                As[r][jcol] = __float2bfloat16(fmaxf(h, 0.0f));
            }
        }
        {
            const uint4* src = (const uint4*)(w2t + (size_t)(n0 + bn) * C_DIM + k0 + bseg * 8);
            *(uint4*)&Bs[bn][bseg * 8] = *src;
        }
        __syncthreads();
#pragma unroll
        for (int kk = 0; kk < 32; kk += 16) {
            uint32_t a[2][4];
#pragma unroll
            for (int mt = 0; mt < 2; mt++) {
                int r = warp_m * 32 + mt * 16 + gr;
                a[mt][0] = *(const uint32_t*)&As[r    ][kk + 2 * qg];
                a[mt][1] = *(const uint32_t*)&As[r + 8][kk + 2 * qg];
                a[mt][2] = *(const uint32_t*)&As[r    ][kk + 2 * qg + 8];
                a[mt][3] = *(const uint32_t*)&As[r + 8][kk + 2 * qg + 8];
            }
#pragma unroll
            for (int nt = 0; nt < 4; nt++) {
                int nn = warp_n * 32 + nt * 8 + gr;
                uint32_t b0 = *(const uint32_t*)&Bs[nn][kk + 2 * qg];
                uint32_t b1r = *(const uint32_t*)&Bs[nn][kk + 2 * qg + 8];
#pragma unroll
                for (int mt = 0; mt < 2; mt++) {
                    asm volatile(
                        "mma.sync.aligned.m16n8k16.row.col.f32.bf16.bf16.f32 "
                        "{%0,%1,%2,%3}, {%4,%5,%6,%7}, {%8,%9}, {%0,%1,%2,%3};"
                        : "+f"(acc[mt][nt][0]), "+f"(acc[mt][nt][1]),
                          "+f"(acc[mt][nt][2]), "+f"(acc[mt][nt][3])
                        : "r"(a[mt][0]), "r"(a[mt][1]), "r"(a[mt][2]), "r"(a[mt][3]),
                          "r"(b0), "r"(b1r));
                }
            }
        }
    }
    __syncthreads();

#pragma unroll
    for (int mt = 0; mt < 2; mt++) {
#pragma unroll
        for (int nt = 0; nt < 4; nt++) {
            int r = warp_m * 32 + mt * 16 + gr;
            int c = warp_n * 32 + nt * 8 + 2 * qg;
            Cs[r    ][c    ] = acc[mt][nt][0];
            Cs[r    ][c + 1] = acc[mt][nt][1];
            Cs[r + 8][c    ] = acc[mt][nt][2];
            Cs[r + 8][c + 1] = acc[mt][nt][3];
        }
    }
    __syncthreads();

    {
        int p  = tid >> 5;
        int c0 = (tid & 31) * 2;
        int n_pt = pt0 + p;
        float tval0 = g_theta[(size_t)n_pt * C_DIM + n0 + c0];
        float tval1 = g_theta[(size_t)n_pt * C_DIM + n0 + c0 + 1];

#pragma unroll
        for (int cc = 0; cc < 2; cc++) {
            int c = c0 + cc;
            int cg = n0 + c;
            float tv = cc ? tval1 : tval0;
            float bb = b2s[c];
            float df[KNN];
            float mx = -3.4e38f;
#pragma unroll
            for (int k = 0; k < KNN; k++) {
                int j = idxs[p * KNN + k];
                float ph = g_phi[(size_t)j * C_DIM + cg];
                float pe = Cs[p * KNN + k][c] + bb;
                float v = pe * (tv - ph + 1.0f) * 0.0625f;
                df[k] = v;
                mx = fmaxf(mx, v);
            }
            float s = 0.0f;
#pragma unroll
            for (int k = 0; k < KNN; k++) { df[k] = __expf(df[k] - mx); s += df[k]; }
            float inv = 1.0f / s;
            float y = 0.0f;
#pragma unroll
            for (int k = 0; k < KNN; k++) {
                int j = idxs[p * KNN + k];
                y = fmaf(df[k] * inv, g_gf[(size_t)j * C_DIM + cg], y);
            }
            g_y[(size_t)n_pt * C_DIM + cg] = y;
        }
    }
}

// ---------------- launch ----------------------------------------------------
extern "C" void kernel_launch(void* const* d_in, const int* in_sizes, int n_in,
                              void* d_out, int out_size) {
    const float* coords  = (const float*)d_in[0];
    const float* feats   = (const float*)d_in[1];
    const float* theta_w = (const float*)d_in[2];
    const float* theta_b = (const float*)d_in[3];
    const float* phi_w   = (const float*)d_in[4];
    const float* phi_b   = (const float*)d_in[5];
    const float* g_w     = (const float*)d_in[6];
    const float* g_b     = (const float*)d_in[7];
    const float* pe1_w1  = (const float*)d_in[8];
    const float* pe1_b1  = (const float*)d_in[9];
    const float* pe1_w2  = (const float*)d_in[10];
    const float* pe1_b2  = (const float*)d_in[11];
    const float* W_w     = (const float*)d_in[12];
    const float* W_b     = (const float*)d_in[13];
    float* out = (float*)d_out;

    float *p_theta, *p_phi, *p_gf, *p_y;
    cudaGetSymbolAddress((void**)&p_theta, g_theta);
    cudaGetSymbolAddress((void**)&p_phi,   g_phi);
    cudaGetSymbolAddress((void**)&p_gf,    g_gf);
    cudaGetSymbolAddress((void**)&p_y,     g_y);

    knn_kernel2<<<N_PTS / QPB, 256>>>(coords);
    w2_prep_kernel<<<C_DIM * C_DIM / 256, 256>>>(pe1_w2);

    dim3 gt(C_DIM / 64, N_PTS / 128);   // (4, 64)
    gemm_tf32_kernel<<<gt, 256>>>(feats, theta_w, theta_b, p_theta);
    gemm_tf32_kernel<<<gt, 256>>>(feats, phi_w,   phi_b,   p_phi);
    gemm_tf32_kernel<<<gt, 256>>>(feats, g_w,     g_b,     p_gf);

    dim3 g2(C_DIM / 64, N_PTS * KNN / 128);  // (4, 1024)
    pe_attn_kernel<<<g2, 256>>>(pe1_w1, pe1_b1, pe1_b2);

    dim3 g1(C_DIM / BN, N_PTS / BM);
    gemm_bias_kernel<<<g1, 256>>>(p_y, W_w, W_b, feats, out,
                                  N_PTS, C_DIM, C_DIM);
}

// round 8
// speedup vs baseline: 2.5184x; 1.1687x over previous
#include <cuda_runtime.h>
#include <cuda_bf16.h>
#include <math.h>
#include <stdint.h>

#define N_PTS 8192
#define C_DIM 256
#define KNN   16

// ---------------- scratch (device globals; no allocations allowed) ----------
__device__ int   g_idx[N_PTS * KNN];
__device__ float g_delta[N_PTS * KNN * 3];
__device__ float g_theta[N_PTS * C_DIM];
__device__ float g_phi[N_PTS * C_DIM];
__device__ float g_gf[N_PTS * C_DIM];
__device__ float g_y[N_PTS * C_DIM];
__device__ __nv_bfloat16 g_w2t[C_DIM * C_DIM];   // w2 transposed, bf16: [n][k]

// ---------------- KNN v2: 8 threads/query, private top-16 + 8-way merge -----
#define KTILE 512
#define QPB   32
#define TPQ   8

__global__ __launch_bounds__(256) void knn_kernel2(const float* __restrict__ coords) {
    __shared__ float4 sc[KTILE];
    __shared__ float  md[QPB][TPQ][KNN];
    __shared__ int    mi[QPB][TPQ][KNN];

    const int tid = threadIdx.x;
    const int ql  = tid >> 3;
    const int g   = tid & 7;
    const int q   = blockIdx.x * QPB + ql;

    const float qx = coords[q * 3 + 0], qy = coords[q * 3 + 1], qz = coords[q * 3 + 2];
    const float qs = qx * qx + qy * qy + qz * qz;

    float bd[KNN];
    int   bi[KNN];
#pragma unroll
    for (int s = 0; s < KNN; s++) { bd[s] = 3.4e38f; bi[s] = 0x7fffffff; }

    for (int base = 0; base < N_PTS; base += KTILE) {
        __syncthreads();
        for (int t = tid; t < KTILE; t += 256) {
            float x = coords[(base + t) * 3 + 0];
            float y = coords[(base + t) * 3 + 1];
            float z = coords[(base + t) * 3 + 2];
            sc[t] = make_float4(x, y, z, x * x + y * y + z * z);
        }
        __syncthreads();
        const int t0 = g * (KTILE / TPQ);
#pragma unroll 4
        for (int tt = 0; tt < KTILE / TPQ; tt++) {
            float4 cc = sc[t0 + tt];
            float dot = qx * cc.x + qy * cc.y + qz * cc.z;
            float d2 = qs + cc.w - 2.0f * dot;
            if (d2 < bd[KNN - 1]) {
                float cd = d2; int ci = base + t0 + tt;
#pragma unroll
                for (int s = 0; s < KNN; s++) {
                    if (cd < bd[s]) {
                        float td = bd[s]; int ti = bi[s];
                        bd[s] = cd; bi[s] = ci; cd = td; ci = ti;
                    }
                }
            }
        }
    }
#pragma unroll
    for (int s = 0; s < KNN; s++) { md[ql][g][s] = bd[s]; mi[ql][g][s] = bi[s]; }
    __syncthreads();

    if (g == 0) {
        int h[TPQ] = {};
        for (int s = 0; s < KNN; s++) {
            float bdv = 3.4e38f; int biv = 0x7fffffff; int bl = 0;
#pragma unroll
            for (int l = 0; l < TPQ; l++) {
                float d = md[ql][l][h[l]];
                int   i = mi[ql][l][h[l]];
                if (d < bdv || (d == bdv && i < biv)) { bdv = d; biv = i; bl = l; }
            }
            h[bl]++;
            g_idx[q * KNN + s] = biv;
            g_delta[(q * KNN + s) * 3 + 0] = coords[biv * 3 + 0] - qx;
            g_delta[(q * KNN + s) * 3 + 1] = coords[biv * 3 + 1] - qy;
            g_delta[(q * KNN + s) * 3 + 2] = coords[biv * 3 + 2] - qz;
        }
    }
}

// ---------------- tf32 helpers ----------------------------------------------
__device__ __forceinline__ float to_tf32(float x) {
    float r;
    asm("cvt.rna.tf32.f32 %0, %1;" : "=f"(r) : "f"(x));
    return r;
}

#define TA_PAD 36
#define TB_PAD 72

#define MMA_TF32(acc, a, b0, b1)                                               \
    asm volatile(                                                              \
        "mma.sync.aligned.m16n8k8.row.col.f32.tf32.tf32.f32 "                  \
        "{%0,%1,%2,%3}, {%4,%5,%6,%7}, {%8,%9}, {%0,%1,%2,%3};"                \
        : "+f"(acc[0]), "+f"(acc[1]), "+f"(acc[2]), "+f"(acc[3])               \
        : "r"(a[0]), "r"(a[1]), "r"(a[2]), "r"(a[3]), "r"(b0), "r"(b1))

// ---------------- fused theta/phi/g tf32 GEMM -------------------------------
__global__ __launch_bounds__(256) void gemm3_tf32_kernel(
    const float* __restrict__ A,
    const float* __restrict__ B0, const float* __restrict__ B1, const float* __restrict__ B2,
    const float* __restrict__ bias0, const float* __restrict__ bias1, const float* __restrict__ bias2,
    float* __restrict__ C0, float* __restrict__ C1, float* __restrict__ C2)
{
    __shared__ float As[128][TA_PAD];
    __shared__ float Bs[3][32][TB_PAD];

    const int tid  = threadIdx.x;
    const int lane = tid & 31;
    const int wid  = tid >> 5;
    const int warp_m = wid & 3;
    const int warp_n = wid >> 2;
    const int qg = lane & 3;
    const int gr = lane >> 2;

    const int m0 = blockIdx.y * 128;
    const int n0 = blockIdx.x * 64;

    float acc[3][2][4][4] = {};
    const float* Bp[3] = {B0, B1, B2};

    const int ar  = tid >> 1, aseg = tid & 1;
    const int br  = tid >> 3, bseg = tid & 7;

    for (int k0 = 0; k0 < C_DIM; k0 += 32) {
        __syncthreads();
        {
            const float4* src = (const float4*)(A + (size_t)(m0 + ar) * C_DIM + k0 + aseg * 16);
#pragma unroll
            for (int i = 0; i < 4; i++) {
                float4 v = src[i];
                int c = aseg * 16 + i * 4;
                As[ar][c + 0] = to_tf32(v.x); As[ar][c + 1] = to_tf32(v.y);
                As[ar][c + 2] = to_tf32(v.z); As[ar][c + 3] = to_tf32(v.w);
            }
        }
#pragma unroll
        for (int w = 0; w < 3; w++) {
            const float4* src = (const float4*)(Bp[w] + (size_t)(k0 + br) * C_DIM + n0 + bseg * 8);
            float4 v0 = src[0], v1 = src[1];
            int c = bseg * 8;
            Bs[w][br][c + 0] = to_tf32(v0.x); Bs[w][br][c + 1] = to_tf32(v0.y);
            Bs[w][br][c + 2] = to_tf32(v0.z); Bs[w][br][c + 3] = to_tf32(v0.w);
            Bs[w][br][c + 4] = to_tf32(v1.x); Bs[w][br][c + 5] = to_tf32(v1.y);
            Bs[w][br][c + 6] = to_tf32(v1.z); Bs[w][br][c + 7] = to_tf32(v1.w);
        }
        __syncthreads();
#pragma unroll
        for (int kk = 0; kk < 32; kk += 8) {
            uint32_t a[2][4];
#pragma unroll
            for (int mt = 0; mt < 2; mt++) {
                int r = warp_m * 32 + mt * 16 + gr;
                a[mt][0] = __float_as_uint(As[r    ][kk + qg]);
                a[mt][1] = __float_as_uint(As[r + 8][kk + qg]);
                a[mt][2] = __float_as_uint(As[r    ][kk + qg + 4]);
                a[mt][3] = __float_as_uint(As[r + 8][kk + qg + 4]);
            }
#pragma unroll
            for (int w = 0; w < 3; w++) {
#pragma unroll
                for (int nt = 0; nt < 4; nt++) {
                    int n = warp_n * 32 + nt * 8 + gr;
                    uint32_t b0 = __float_as_uint(Bs[w][kk + qg    ][n]);
                    uint32_t b1 = __float_as_uint(Bs[w][kk + qg + 4][n]);
#pragma unroll
                    for (int mt = 0; mt < 2; mt++) MMA_TF32(acc[w][mt][nt], a[mt], b0, b1);
                }
            }
        }
    }
    const float* biasp[3] = {bias0, bias1, bias2};
    float* Cp[3] = {C0, C1, C2};
#pragma unroll
    for (int w = 0; w < 3; w++) {
#pragma unroll
        for (int mt = 0; mt < 2; mt++) {
#pragma unroll
            for (int nt = 0; nt < 4; nt++) {
                int r = warp_m * 32 + mt * 16 + gr;
                int c = warp_n * 32 + nt * 8 + 2 * qg;
                int n = n0 + c;
                float bn0 = biasp[w][n], bn1 = biasp[w][n + 1];
                float2 v0 = make_float2(acc[w][mt][nt][0] + bn0, acc[w][mt][nt][1] + bn1);
                float2 v1 = make_float2(acc[w][mt][nt][2] + bn0, acc[w][mt][nt][3] + bn1);
                *(float2*)(Cp[w] + (size_t)(m0 + r    ) * C_DIM + n) = v0;
                *(float2*)(Cp[w] + (size_t)(m0 + r + 8) * C_DIM + n) = v1;
            }
        }
    }
}

// ---------------- tf32 GEMM with bias + residual (final W layer) ------------
__global__ __launch_bounds__(256) void gemm_tf32_resid_kernel(
    const float* __restrict__ A, const float* __restrict__ B,
    const float* __restrict__ bias, const float* __restrict__ resid,
    float* __restrict__ Cout)
{
    __shared__ float As[128][TA_PAD];
    __shared__ float Bs[32][TB_PAD];

    const int tid  = threadIdx.x;
    const int lane = tid & 31;
    const int wid  = tid >> 5;
    const int warp_m = wid & 3;
    const int warp_n = wid >> 2;
    const int qg = lane & 3;
    const int gr = lane >> 2;

    const int m0 = blockIdx.y * 128;
    const int n0 = blockIdx.x * 64;

    float acc[2][4][4] = {};

    const int ar  = tid >> 1, aseg = tid & 1;
    const int br  = tid >> 3, bseg = tid & 7;

    for (int k0 = 0; k0 < C_DIM; k0 += 32) {
        __syncthreads();
        {
            const float4* src = (const float4*)(A + (size_t)(m0 + ar) * C_DIM + k0 + aseg * 16);
#pragma unroll
            for (int i = 0; i < 4; i++) {
                float4 v = src[i];
                int c = aseg * 16 + i * 4;
                As[ar][c + 0] = to_tf32(v.x); As[ar][c + 1] = to_tf32(v.y);
                As[ar][c + 2] = to_tf32(v.z); As[ar][c + 3] = to_tf32(v.w);
            }
        }
        {
            const float4* src = (const float4*)(B + (size_t)(k0 + br) * C_DIM + n0 + bseg * 8);
            float4 v0 = src[0], v1 = src[1];
            int c = bseg * 8;
            Bs[br][c + 0] = to_tf32(v0.x); Bs[br][c + 1] = to_tf32(v0.y);
            Bs[br][c + 2] = to_tf32(v0.z); Bs[br][c + 3] = to_tf32(v0.w);
            Bs[br][c + 4] = to_tf32(v1.x); Bs[br][c + 5] = to_tf32(v1.y);
            Bs[br][c + 6] = to_tf32(v1.z); Bs[br][c + 7] = to_tf32(v1.w);
        }
        __syncthreads();
#pragma unroll
        for (int kk = 0; kk < 32; kk += 8) {
            uint32_t a[2][4];
#pragma unroll
            for (int mt = 0; mt < 2; mt++) {
                int r = warp_m * 32 + mt * 16 + gr;
                a[mt][0] = __float_as_uint(As[r    ][kk + qg]);
                a[mt][1] = __float_as_uint(As[r + 8][kk + qg]);
                a[mt][2] = __float_as_uint(As[r    ][kk + qg + 4]);
                a[mt][3] = __float_as_uint(As[r + 8][kk + qg + 4]);
            }
#pragma unroll
            for (int nt = 0; nt < 4; nt++) {
                int n = warp_n * 32 + nt * 8 + gr;
                uint32_t b0 = __float_as_uint(Bs[kk + qg    ][n]);
                uint32_t b1 = __float_as_uint(Bs[kk + qg + 4][n]);
#pragma unroll
                for (int mt = 0; mt < 2; mt++) MMA_TF32(acc[mt][nt], a[mt], b0, b1);
            }
        }
    }
#pragma unroll
    for (int mt = 0; mt < 2; mt++) {
#pragma unroll
        for (int nt = 0; nt < 4; nt++) {
            int r = warp_m * 32 + mt * 16 + gr;
            int c = warp_n * 32 + nt * 8 + 2 * qg;
            int n = n0 + c;
            float bn0 = bias[n], bn1 = bias[n + 1];
            float2 r0 = *(const float2*)(resid + (size_t)(m0 + r    ) * C_DIM + n);
            float2 r1 = *(const float2*)(resid + (size_t)(m0 + r + 8) * C_DIM + n);
            float2 v0 = make_float2(acc[mt][nt][0] + bn0 + r0.x, acc[mt][nt][1] + bn1 + r0.y);
            float2 v1 = make_float2(acc[mt][nt][2] + bn0 + r1.x, acc[mt][nt][3] + bn1 + r1.y);
            *(float2*)(Cout + (size_t)(m0 + r    ) * C_DIM + n) = v0;
            *(float2*)(Cout + (size_t)(m0 + r + 8) * C_DIM + n) = v1;
        }
    }
}

// ---------------- prep: w2 -> bf16 transposed --------------------------------
__global__ void w2_prep_kernel(const float* __restrict__ w2) {
    int t = blockIdx.x * blockDim.x + threadIdx.x;
    int n = t >> 8, k = t & 255;
    g_w2t[n * C_DIM + k] = __float2bfloat16(w2[k * C_DIM + n]);
}

// ---------------- pe_attn v3: v2 mainloop (B-load FIXED) + smem epilogue ----
#define A_STRIDE 264   // bf16 elems; 132 words, 132%32==4 -> conflict-free frags
#define B_STRIDE 72    // bf16 elems
#define C_STRIDE 260   // fp32 words
#define SMEM_A_BYTES (128 * A_STRIDE * 2)                 // 67584
#define SMEM_B_BYTES (256 * B_STRIDE * 2)                 // 36864
#define SMEM_C_BYTES (128 * C_STRIDE * 4)                 // 133120 (unions over A+B)
#define SMEM_DS_OFF  SMEM_C_BYTES                         // 133120
#define SMEM_IDX_OFF (SMEM_DS_OFF + 128 * 3 * 4)          // 134656
#define SMEM_TOTAL_PE (SMEM_IDX_OFF + 128 * 4)            // 135168

#define MMA_BF16(acc, a, b0, b1)                                               \
    asm volatile(                                                              \
        "mma.sync.aligned.m16n8k16.row.col.f32.bf16.bf16.f32 "                 \
        "{%0,%1,%2,%3}, {%4,%5,%6,%7}, {%8,%9}, {%0,%1,%2,%3};"                \
        : "+f"(acc[0]), "+f"(acc[1]), "+f"(acc[2]), "+f"(acc[3])               \
        : "r"(a[0]), "r"(a[1]), "r"(a[2]), "r"(a[3]), "r"(b0), "r"(b1))

__global__ __launch_bounds__(512, 1) void pe_attn3_kernel(
    const float* __restrict__ w1, const float* __restrict__ b1,
    const float* __restrict__ b2)
{
    extern __shared__ __align__(16) char sm[];
    __nv_bfloat16* Asm = (__nv_bfloat16*)sm;
    __nv_bfloat16* Bsm = (__nv_bfloat16*)(sm + SMEM_A_BYTES);
    float* Cs   = (float*)sm;                      // union over A+B after mainloop
    float* ds   = (float*)(sm + SMEM_DS_OFF);
    int*   idxs = (int*)(sm + SMEM_IDX_OFF);

    const int tid  = threadIdx.x;
    const int lane = tid & 31;
    const int wid  = tid >> 5;
    const int warp_m = wid & 3;      // 4 x 32 rows
    const int warp_n = wid >> 2;     // 4 x 64 cols
    const int qg = lane & 3;
    const int gr = lane >> 2;

    const int m0  = blockIdx.x * 128;
    const int pt0 = blockIdx.x * 8;

    if (tid < 384) ds[tid] = g_delta[(size_t)m0 * 3 + tid];
    if (tid < 128) idxs[tid] = g_idx[pt0 * KNN + tid];
    __syncthreads();

    // ---- A-gen once: As[r][j] = relu(delta[r] . w1[:,j] + b1[j]) ----
    {
        int jj = tid & 255, rh = tid >> 8;
        float wa = w1[jj], wb = w1[C_DIM + jj], wc = w1[2 * C_DIM + jj];
        float bb = b1[jj];
#pragma unroll 8
        for (int i = 0; i < 64; i++) {
            int r = rh * 64 + i;
            float h = fmaf(ds[r * 3 + 0], wa,
                      fmaf(ds[r * 3 + 1], wb,
                      fmaf(ds[r * 3 + 2], wc, bb)));
            Asm[r * A_STRIDE + jj] = __float2bfloat16(fmaxf(h, 0.0f));
        }
    }

    float acc[2][8][4] = {};

    const int bn = tid >> 1, bh = tid & 1;   // B chunk load mapping

    for (int c0 = 0; c0 < 4; c0++) {
        __syncthreads();
        {
            // FIX (R5/R7 bug): each thread owns 32 bf16 = 64 B = 4 uint4;
            // previous version only copied 2 uint4, leaving half of Bsm garbage.
            const uint4* src = (const uint4*)(g_w2t + (size_t)bn * C_DIM + c0 * 64 + bh * 32);
            uint4* dst = (uint4*)(Bsm + bn * B_STRIDE + bh * 32);
            dst[0] = src[0]; dst[1] = src[1]; dst[2] = src[2]; dst[3] = src[3];
        }
        __syncthreads();
#pragma unroll
        for (int kk = 0; kk < 64; kk += 16) {
            const int ka = c0 * 64 + kk;
            uint32_t a[2][4];
#pragma unroll
            for (int mt = 0; mt < 2; mt++) {
                int r = warp_m * 32 + mt * 16 + gr;
                const __nv_bfloat16* ap = Asm + r * A_STRIDE + ka + 2 * qg;
                a[mt][0] = *(const uint32_t*)ap;
                a[mt][1] = *(const uint32_t*)(ap + 8 * A_STRIDE);
                a[mt][2] = *(const uint32_t*)(ap + 8);
                a[mt][3] = *(const uint32_t*)(ap + 8 * A_STRIDE + 8);
            }
#pragma unroll
            for (int nt = 0; nt < 8; nt++) {
                int nn = warp_n * 64 + nt * 8 + gr;
                const __nv_bfloat16* bp = Bsm + nn * B_STRIDE + kk + 2 * qg;
                uint32_t b0  = *(const uint32_t*)bp;
                uint32_t b1r = *(const uint32_t*)(bp + 8);
#pragma unroll
                for (int mt = 0; mt < 2; mt++) MMA_BF16(acc[mt][nt], a[mt], b0, b1r);
            }
        }
    }

    // ---- all warps done with Asm/Bsm; overlay Cs and dump (R4-proven map) ---
    __syncthreads();
#pragma unroll
    for (int mt = 0; mt < 2; mt++) {
#pragma unroll
        for (int nt = 0; nt < 8; nt++) {
            int r = warp_m * 32 + mt * 16 + gr;
            int c = warp_n * 64 + nt * 8 + 2 * qg;
            Cs[(r    ) * C_STRIDE + c    ] = acc[mt][nt][0];
            Cs[(r    ) * C_STRIDE + c + 1] = acc[mt][nt][1];
            Cs[(r + 8) * C_STRIDE + c    ] = acc[mt][nt][2];
            Cs[(r + 8) * C_STRIDE + c + 1] = acc[mt][nt][3];
        }
    }
    __syncthreads();

    // ---- R4-proven per-thread softmax epilogue ----
    // 512 threads: p = tid>>6 (8 points), base channel = tid&63, 4 chunks of 64.
    {
        int p  = tid >> 6;
        int cb = tid & 63;
        int n_pt = pt0 + p;
#pragma unroll
        for (int cc = 0; cc < 4; cc++) {
            int c = cb + cc * 64;
            float tv = g_theta[(size_t)n_pt * C_DIM + c];
            float bb = b2[c];
            float df[KNN];
            float mx = -3.4e38f;
#pragma unroll
            for (int k = 0; k < KNN; k++) {
                int j = idxs[p * KNN + k];
                float ph = g_phi[(size_t)j * C_DIM + c];
                float pe = Cs[(p * KNN + k) * C_STRIDE + c] + bb;
                float v = pe * (tv - ph + 1.0f) * 0.0625f;
                df[k] = v;
                mx = fmaxf(mx, v);
            }
            float s = 0.0f;
#pragma unroll
            for (int k = 0; k < KNN; k++) { df[k] = __expf(df[k] - mx); s += df[k]; }
            float inv = 1.0f / s;
            float y = 0.0f;
#pragma unroll
            for (int k = 0; k < KNN; k++) {
                int j = idxs[p * KNN + k];
                y = fmaf(df[k] * inv, g_gf[(size_t)j * C_DIM + c], y);
            }
            g_y[(size_t)n_pt * C_DIM + c] = y;
        }
    }
}

// ---------------- launch ----------------------------------------------------
extern "C" void kernel_launch(void* const* d_in, const int* in_sizes, int n_in,
                              void* d_out, int out_size) {
    const float* coords  = (const float*)d_in[0];
    const float* feats   = (const float*)d_in[1];
    const float* theta_w = (const float*)d_in[2];
    const float* theta_b = (const float*)d_in[3];
    const float* phi_w   = (const float*)d_in[4];
    const float* phi_b   = (const float*)d_in[5];
    const float* g_w     = (const float*)d_in[6];
    const float* g_b     = (const float*)d_in[7];
    const float* pe1_w1  = (const float*)d_in[8];
    const float* pe1_b1  = (const float*)d_in[9];
    const float* pe1_w2  = (const float*)d_in[10];
    const float* pe1_b2  = (const float*)d_in[11];
    const float* W_w     = (const float*)d_in[12];
    const float* W_b     = (const float*)d_in[13];
    float* out = (float*)d_out;

    float *p_theta, *p_phi, *p_gf, *p_y;
    cudaGetSymbolAddress((void**)&p_theta, g_theta);
    cudaGetSymbolAddress((void**)&p_phi,   g_phi);
    cudaGetSymbolAddress((void**)&p_gf,    g_gf);
    cudaGetSymbolAddress((void**)&p_y,     g_y);

    cudaFuncSetAttribute(pe_attn3_kernel,
                         cudaFuncAttributeMaxDynamicSharedMemorySize, SMEM_TOTAL_PE);

    knn_kernel2<<<N_PTS / QPB, 256>>>(coords);
    w2_prep_kernel<<<C_DIM * C_DIM / 256, 256>>>(pe1_w2);

    dim3 gt(C_DIM / 64, N_PTS / 128);   // (4, 64)
    gemm3_tf32_kernel<<<gt, 256>>>(feats, theta_w, phi_w, g_w,
                                   theta_b, phi_b, g_b,
                                   p_theta, p_phi, p_gf);

    pe_attn3_kernel<<<N_PTS * KNN / 128, 512, SMEM_TOTAL_PE>>>(pe1_w1, pe1_b1, pe1_b2);

    gemm_tf32_resid_kernel<<<gt, 256>>>(p_y, W_w, W_b, feats, out);
}

// round 9
// speedup vs baseline: 4.0444x; 1.6060x over previous
#include <cuda_runtime.h>
#include <cuda_bf16.h>
#include <math.h>
#include <stdint.h>

#define N_PTS 8192
#define C_DIM 256
#define KNN   16

// ---------------- scratch (device globals; no allocations allowed) ----------
__device__ int   g_idx[N_PTS * KNN];
__device__ float g_delta[N_PTS * KNN * 3];
__device__ float g_theta[N_PTS * C_DIM];
__device__ float g_phi[N_PTS * C_DIM];
__device__ float g_gf[N_PTS * C_DIM];
__device__ float g_y[N_PTS * C_DIM];
__device__ __nv_bfloat16 g_w2t[C_DIM * C_DIM];   // w2 transposed, bf16: [n][k]

// ---------------- grid-KNN scratch ------------------------------------------
#define GRES   16
#define NCELLS (GRES * GRES * GRES)
#define CELLSZ 6.25f
__device__ int    g_cell_cnt[NCELLS];
__device__ int    g_cell_off[NCELLS + 1];
__device__ int    g_cell_cur[NCELLS];
__device__ float4 g_sorted[N_PTS];     // (x, y, z, bitcast orig idx)

__device__ __forceinline__ int cell_coord(float x) {
    int c = (int)(x * 0.16f);          // 16 / 100
    return min(GRES - 1, max(0, c));
}

__global__ void cell_zero_kernel() {
    g_cell_cnt[blockIdx.x * 256 + threadIdx.x] = 0;
}

__global__ void cell_count_kernel(const float* __restrict__ coords) {
    int q = blockIdx.x * 256 + threadIdx.x;
    int cx = cell_coord(coords[q * 3 + 0]);
    int cy = cell_coord(coords[q * 3 + 1]);
    int cz = cell_coord(coords[q * 3 + 2]);
    atomicAdd(&g_cell_cnt[(cx * GRES + cy) * GRES + cz], 1);
}

// single block, 512 threads, 8 cells each: exclusive prefix sum over 4096
__global__ void cell_scan_kernel() {
    __shared__ int part[512];
    int t = threadIdx.x;
    int base = t * 8;
    int loc[8];
    int s = 0;
#pragma unroll
    for (int i = 0; i < 8; i++) { loc[i] = g_cell_cnt[base + i]; s += loc[i]; }
    part[t] = s;
    __syncthreads();
    for (int off = 1; off < 512; off <<= 1) {
        int v = (t >= off) ? part[t - off] : 0;
        __syncthreads();
        part[t] += v;
        __syncthreads();
    }
    int run = part[t] - s;   // exclusive prefix of this thread's chunk
#pragma unroll
    for (int i = 0; i < 8; i++) {
        g_cell_off[base + i] = run;
        g_cell_cur[base + i] = run;
        run += loc[i];
    }
    if (t == 511) g_cell_off[NCELLS] = run;
}

__global__ void cell_scatter_kernel(const float* __restrict__ coords) {
    int q = blockIdx.x * 256 + threadIdx.x;
    float x = coords[q * 3 + 0], y = coords[q * 3 + 1], z = coords[q * 3 + 2];
    int cell = (cell_coord(x) * GRES + cell_coord(y)) * GRES + cell_coord(z);
    int pos = atomicAdd(&g_cell_cur[cell], 1);
    g_sorted[pos] = make_float4(x, y, z, __int_as_float(q));
}

// ---------------- grid KNN: exact top-16 via expanding Chebyshev rings ------
// Ring r+1 points are >= r*CELLSZ from the query, so stopping once
// kth_d2 < (r*CELLSZ)^2 after ring r is exact. Lexicographic (d2, idx)
// comparator == jax.lax.top_k stable order, independent of scatter order.
__global__ __launch_bounds__(128) void knn_grid_kernel(const float* __restrict__ coords) {
    int sp = blockIdx.x * 128 + threadIdx.x;    // sorted position (spatially coherent)
    float4 me = g_sorted[sp];
    const float qx = me.x, qy = me.y, qz = me.z;
    const int q = __float_as_int(me.w);
    const float qs = qx * qx + qy * qy + qz * qz;
    const int cx = cell_coord(qx), cy = cell_coord(qy), cz = cell_coord(qz);

    float bd[KNN];
    int   bi[KNN];
#pragma unroll
    for (int s = 0; s < KNN; s++) { bd[s] = 3.4e38f; bi[s] = 0x7fffffff; }

    for (int r = 0; r < GRES; r++) {
        int x0 = max(cx - r, 0), x1 = min(cx + r, GRES - 1);
        int y0 = max(cy - r, 0), y1 = min(cy + r, GRES - 1);
        int z0 = max(cz - r, 0), z1 = min(cz + r, GRES - 1);
        for (int ix = x0; ix <= x1; ix++) {
            int dxa = abs(ix - cx);
            for (int iy = y0; iy <= y1; iy++) {
                int chebxy = max(dxa, abs(iy - cy));
                for (int iz = z0; iz <= z1; iz++) {
                    if (max(chebxy, abs(iz - cz)) != r) continue;
                    int cell = (ix * GRES + iy) * GRES + iz;
                    int p1 = g_cell_off[cell + 1];
                    for (int p = g_cell_off[cell]; p < p1; p++) {
                        float4 c = g_sorted[p];
                        float cs2 = c.x * c.x + c.y * c.y + c.z * c.z;
                        float dot = qx * c.x + qy * c.y + qz * c.z;
                        float d2 = qs + cs2 - 2.0f * dot;
                        int ci = __float_as_int(c.w);
                        if (d2 < bd[KNN - 1] ||
                            (d2 == bd[KNN - 1] && ci < bi[KNN - 1])) {
                            float cd = d2; int cidx = ci;
#pragma unroll
                            for (int s = 0; s < KNN; s++) {
                                if (cd < bd[s] || (cd == bd[s] && cidx < bi[s])) {
                                    float td = bd[s]; int ti = bi[s];
                                    bd[s] = cd; bi[s] = cidx; cd = td; cidx = ti;
                                }
                            }
                        }
                    }
                }
            }
        }
        float rr = (float)r * CELLSZ;
        if (bd[KNN - 1] < rr * rr) break;   // strict: next ring can't beat or tie-win
    }

#pragma unroll
    for (int s = 0; s < KNN; s++) {
        int j = bi[s];
        g_idx[q * KNN + s] = j;
        g_delta[(q * KNN + s) * 3 + 0] = coords[j * 3 + 0] - qx;
        g_delta[(q * KNN + s) * 3 + 1] = coords[j * 3 + 1] - qy;
        g_delta[(q * KNN + s) * 3 + 2] = coords[j * 3 + 2] - qz;
    }
}

// ---------------- tf32 helpers ----------------------------------------------
__device__ __forceinline__ float to_tf32(float x) {
    float r;
    asm("cvt.rna.tf32.f32 %0, %1;" : "=f"(r) : "f"(x));
    return r;
}

#define TA_PAD 36
#define TB_PAD 72

#define MMA_TF32(acc, a, b0, b1)                                               \
    asm volatile(                                                              \
        "mma.sync.aligned.m16n8k8.row.col.f32.tf32.tf32.f32 "                  \
        "{%0,%1,%2,%3}, {%4,%5,%6,%7}, {%8,%9}, {%0,%1,%2,%3};"                \
        : "+f"(acc[0]), "+f"(acc[1]), "+f"(acc[2]), "+f"(acc[3])               \
        : "r"(a[0]), "r"(a[1]), "r"(a[2]), "r"(a[3]), "r"(b0), "r"(b1))

// ---------------- fused theta/phi/g tf32 GEMM -------------------------------
__global__ __launch_bounds__(256) void gemm3_tf32_kernel(
    const float* __restrict__ A,
    const float* __restrict__ B0, const float* __restrict__ B1, const float* __restrict__ B2,
    const float* __restrict__ bias0, const float* __restrict__ bias1, const float* __restrict__ bias2,
    float* __restrict__ C0, float* __restrict__ C1, float* __restrict__ C2)
{
    __shared__ float As[128][TA_PAD];
    __shared__ float Bs[3][32][TB_PAD];

    const int tid  = threadIdx.x;
    const int lane = tid & 31;
    const int wid  = tid >> 5;
    const int warp_m = wid & 3;
    const int warp_n = wid >> 2;
    const int qg = lane & 3;
    const int gr = lane >> 2;

    const int m0 = blockIdx.y * 128;
    const int n0 = blockIdx.x * 64;

    float acc[3][2][4][4] = {};
    const float* Bp[3] = {B0, B1, B2};

    const int ar  = tid >> 1, aseg = tid & 1;
    const int br  = tid >> 3, bseg = tid & 7;

    for (int k0 = 0; k0 < C_DIM; k0 += 32) {
        __syncthreads();
        {
            const float4* src = (const float4*)(A + (size_t)(m0 + ar) * C_DIM + k0 + aseg * 16);
#pragma unroll
            for (int i = 0; i < 4; i++) {
                float4 v = src[i];
                int c = aseg * 16 + i * 4;
                As[ar][c + 0] = to_tf32(v.x); As[ar][c + 1] = to_tf32(v.y);
                As[ar][c + 2] = to_tf32(v.z); As[ar][c + 3] = to_tf32(v.w);
            }
        }
#pragma unroll
        for (int w = 0; w < 3; w++) {
            const float4* src = (const float4*)(Bp[w] + (size_t)(k0 + br) * C_DIM + n0 + bseg * 8);
            float4 v0 = src[0], v1 = src[1];
            int c = bseg * 8;
            Bs[w][br][c + 0] = to_tf32(v0.x); Bs[w][br][c + 1] = to_tf32(v0.y);
            Bs[w][br][c + 2] = to_tf32(v0.z); Bs[w][br][c + 3] = to_tf32(v0.w);
            Bs[w][br][c + 4] = to_tf32(v1.x); Bs[w][br][c + 5] = to_tf32(v1.y);
            Bs[w][br][c + 6] = to_tf32(v1.z); Bs[w][br][c + 7] = to_tf32(v1.w);
        }
        __syncthreads();
#pragma unroll
        for (int kk = 0; kk < 32; kk += 8) {
            uint32_t a[2][4];
#pragma unroll
            for (int mt = 0; mt < 2; mt++) {
                int r = warp_m * 32 + mt * 16 + gr;
                a[mt][0] = __float_as_uint(As[r    ][kk + qg]);
                a[mt][1] = __float_as_uint(As[r + 8][kk + qg]);
                a[mt][2] = __float_as_uint(As[r    ][kk + qg + 4]);
                a[mt][3] = __float_as_uint(As[r + 8][kk + qg + 4]);
            }
#pragma unroll
            for (int w = 0; w < 3; w++) {
#pragma unroll
                for (int nt = 0; nt < 4; nt++) {
                    int n = warp_n * 32 + nt * 8 + gr;
                    uint32_t b0 = __float_as_uint(Bs[w][kk + qg    ][n]);
                    uint32_t b1 = __float_as_uint(Bs[w][kk + qg + 4][n]);
#pragma unroll
                    for (int mt = 0; mt < 2; mt++) MMA_TF32(acc[w][mt][nt], a[mt], b0, b1);
                }
            }
        }
    }
    const float* biasp[3] = {bias0, bias1, bias2};
    float* Cp[3] = {C0, C1, C2};
#pragma unroll
    for (int w = 0; w < 3; w++) {
#pragma unroll
        for (int mt = 0; mt < 2; mt++) {
#pragma unroll
            for (int nt = 0; nt < 4; nt++) {
                int r = warp_m * 32 + mt * 16 + gr;
                int c = warp_n * 32 + nt * 8 + 2 * qg;
                int n = n0 + c;
                float bn0 = biasp[w][n], bn1 = biasp[w][n + 1];
                float2 v0 = make_float2(acc[w][mt][nt][0] + bn0, acc[w][mt][nt][1] + bn1);
                float2 v1 = make_float2(acc[w][mt][nt][2] + bn0, acc[w][mt][nt][3] + bn1);
                *(float2*)(Cp[w] + (size_t)(m0 + r    ) * C_DIM + n) = v0;
                *(float2*)(Cp[w] + (size_t)(m0 + r + 8) * C_DIM + n) = v1;
            }
        }
    }
}

// ---------------- tf32 GEMM with bias + residual (final W layer) ------------
__global__ __launch_bounds__(256) void gemm_tf32_resid_kernel(
    const float* __restrict__ A, const float* __restrict__ B,
    const float* __restrict__ bias, const float* __restrict__ resid,
    float* __restrict__ Cout)
{
    __shared__ float As[128][TA_PAD];
    __shared__ float Bs[32][TB_PAD];

    const int tid  = threadIdx.x;
    const int lane = tid & 31;
    const int wid  = tid >> 5;
    const int warp_m = wid & 3;
    const int warp_n = wid >> 2;
    const int qg = lane & 3;
    const int gr = lane >> 2;

    const int m0 = blockIdx.y * 128;
    const int n0 = blockIdx.x * 64;

    float acc[2][4][4] = {};

    const int ar  = tid >> 1, aseg = tid & 1;
    const int br  = tid >> 3, bseg = tid & 7;

    for (int k0 = 0; k0 < C_DIM; k0 += 32) {
        __syncthreads();
        {
            const float4* src = (const float4*)(A + (size_t)(m0 + ar) * C_DIM + k0 + aseg * 16);
#pragma unroll
            for (int i = 0; i < 4; i++) {
                float4 v = src[i];
                int c = aseg * 16 + i * 4;
                As[ar][c + 0] = to_tf32(v.x); As[ar][c + 1] = to_tf32(v.y);
                As[ar][c + 2] = to_tf32(v.z); As[ar][c + 3] = to_tf32(v.w);
            }
        }
        {
            const float4* src = (const float4*)(B + (size_t)(k0 + br) * C_DIM + n0 + bseg * 8);
            float4 v0 = src[0], v1 = src[1];
            int c = bseg * 8;
            Bs[br][c + 0] = to_tf32(v0.x); Bs[br][c + 1] = to_tf32(v0.y);
            Bs[br][c + 2] = to_tf32(v0.z); Bs[br][c + 3] = to_tf32(v0.w);
            Bs[br][c + 4] = to_tf32(v1.x); Bs[br][c + 5] = to_tf32(v1.y);
            Bs[br][c + 6] = to_tf32(v1.z); Bs[br][c + 7] = to_tf32(v1.w);
        }
        __syncthreads();
#pragma unroll
        for (int kk = 0; kk < 32; kk += 8) {
            uint32_t a[2][4];
#pragma unroll
            for (int mt = 0; mt < 2; mt++) {
                int r = warp_m * 32 + mt * 16 + gr;
                a[mt][0] = __float_as_uint(As[r    ][kk + qg]);
                a[mt][1] = __float_as_uint(As[r + 8][kk + qg]);
                a[mt][2] = __float_as_uint(As[r    ][kk + qg + 4]);
                a[mt][3] = __float_as_uint(As[r + 8][kk + qg + 4]);
            }
#pragma unroll
            for (int nt = 0; nt < 4; nt++) {
                int n = warp_n * 32 + nt * 8 + gr;
                uint32_t b0 = __float_as_uint(Bs[kk + qg    ][n]);
                uint32_t b1 = __float_as_uint(Bs[kk + qg + 4][n]);
#pragma unroll
                for (int mt = 0; mt < 2; mt++) MMA_TF32(acc[mt][nt], a[mt], b0, b1);
            }
        }
    }
#pragma unroll
    for (int mt = 0; mt < 2; mt++) {
#pragma unroll
        for (int nt = 0; nt < 4; nt++) {
            int r = warp_m * 32 + mt * 16 + gr;
            int c = warp_n * 32 + nt * 8 + 2 * qg;
            int n = n0 + c;
            float bn0 = bias[n], bn1 = bias[n + 1];
            float2 r0 = *(const float2*)(resid + (size_t)(m0 + r    ) * C_DIM + n);
            float2 r1 = *(const float2*)(resid + (size_t)(m0 + r + 8) * C_DIM + n);
            float2 v0 = make_float2(acc[mt][nt][0] + bn0 + r0.x, acc[mt][nt][1] + bn1 + r0.y);
            float2 v1 = make_float2(acc[mt][nt][2] + bn0 + r1.x, acc[mt][nt][3] + bn1 + r1.y);
            *(float2*)(Cout + (size_t)(m0 + r    ) * C_DIM + n) = v0;
            *(float2*)(Cout + (size_t)(m0 + r + 8) * C_DIM + n) = v1;
        }
    }
}

// ---------------- prep: w2 -> bf16 transposed --------------------------------
__global__ void w2_prep_kernel(const float* __restrict__ w2) {
    int t = blockIdx.x * blockDim.x + threadIdx.x;
    int n = t >> 8, k = t & 255;
    g_w2t[n * C_DIM + k] = __float2bfloat16(w2[k * C_DIM + n]);
}

// ---------------- pe_attn v3 (R8-passing): mainloop + smem epilogue ---------
#define A_STRIDE 264   // bf16 elems; 132 words, 132%32==4 -> conflict-free frags
#define B_STRIDE 72    // bf16 elems
#define C_STRIDE 260   // fp32 words
#define SMEM_A_BYTES (128 * A_STRIDE * 2)                 // 67584
#define SMEM_B_BYTES (256 * B_STRIDE * 2)                 // 36864
#define SMEM_C_BYTES (128 * C_STRIDE * 4)                 // 133120 (unions over A+B)
#define SMEM_DS_OFF  SMEM_C_BYTES                         // 133120
#define SMEM_IDX_OFF (SMEM_DS_OFF + 128 * 3 * 4)          // 134656
#define SMEM_TOTAL_PE (SMEM_IDX_OFF + 128 * 4)            // 135168

#define MMA_BF16(acc, a, b0, b1)                                               \
    asm volatile(                                                              \
        "mma.sync.aligned.m16n8k16.row.col.f32.bf16.bf16.f32 "                 \
        "{%0,%1,%2,%3}, {%4,%5,%6,%7}, {%8,%9}, {%0,%1,%2,%3};"                \
        : "+f"(acc[0]), "+f"(acc[1]), "+f"(acc[2]), "+f"(acc[3])               \
        : "r"(a[0]), "r"(a[1]), "r"(a[2]), "r"(a[3]), "r"(b0), "r"(b1))

__global__ __launch_bounds__(512, 1) void pe_attn3_kernel(
    const float* __restrict__ w1, const float* __restrict__ b1,
    const float* __restrict__ b2)
{
    extern __shared__ __align__(16) char sm[];
    __nv_bfloat16* Asm = (__nv_bfloat16*)sm;
    __nv_bfloat16* Bsm = (__nv_bfloat16*)(sm + SMEM_A_BYTES);
    float* Cs   = (float*)sm;                      // union over A+B after mainloop
    float* ds   = (float*)(sm + SMEM_DS_OFF);
    int*   idxs = (int*)(sm + SMEM_IDX_OFF);

    const int tid  = threadIdx.x;
    const int lane = tid & 31;
    const int wid  = tid >> 5;
    const int warp_m = wid & 3;      // 4 x 32 rows
    const int warp_n = wid >> 2;     // 4 x 64 cols
    const int qg = lane & 3;
    const int gr = lane >> 2;

    const int m0  = blockIdx.x * 128;
    const int pt0 = blockIdx.x * 8;

    if (tid < 384) ds[tid] = g_delta[(size_t)m0 * 3 + tid];
    if (tid < 128) idxs[tid] = g_idx[pt0 * KNN + tid];
    __syncthreads();

    // ---- A-gen once: As[r][j] = relu(delta[r] . w1[:,j] + b1[j]) ----
    {
        int jj = tid & 255, rh = tid >> 8;
        float wa = w1[jj], wb = w1[C_DIM + jj], wc = w1[2 * C_DIM + jj];
        float bb = b1[jj];
#pragma unroll 8
        for (int i = 0; i < 64; i++) {
            int r = rh * 64 + i;
            float h = fmaf(ds[r * 3 + 0], wa,
                      fmaf(ds[r * 3 + 1], wb,
                      fmaf(ds[r * 3 + 2], wc, bb)));
            Asm[r * A_STRIDE + jj] = __float2bfloat16(fmaxf(h, 0.0f));
        }
    }

    float acc[2][8][4] = {};

    const int bn = tid >> 1, bh = tid & 1;   // B chunk load mapping

    for (int c0 = 0; c0 < 4; c0++) {
        __syncthreads();
        {
            const uint4* src = (const uint4*)(g_w2t + (size_t)bn * C_DIM + c0 * 64 + bh * 32);
            uint4* dst = (uint4*)(Bsm + bn * B_STRIDE + bh * 32);
            dst[0] = src[0]; dst[1] = src[1]; dst[2] = src[2]; dst[3] = src[3];
        }
        __syncthreads();
#pragma unroll
        for (int kk = 0; kk < 64; kk += 16) {
            const int ka = c0 * 64 + kk;
            uint32_t a[2][4];
#pragma unroll
            for (int mt = 0; mt < 2; mt++) {
                int r = warp_m * 32 + mt * 16 + gr;
                const __nv_bfloat16* ap = Asm + r * A_STRIDE + ka + 2 * qg;
                a[mt][0] = *(const uint32_t*)ap;
                a[mt][1] = *(const uint32_t*)(ap + 8 * A_STRIDE);
                a[mt][2] = *(const uint32_t*)(ap + 8);
                a[mt][3] = *(const uint32_t*)(ap + 8 * A_STRIDE + 8);
            }
#pragma unroll
            for (int nt = 0; nt < 8; nt++) {
                int nn = warp_n * 64 + nt * 8 + gr;
                const __nv_bfloat16* bp = Bsm + nn * B_STRIDE + kk + 2 * qg;
                uint32_t b0  = *(const uint32_t*)bp;
                uint32_t b1r = *(const uint32_t*)(bp + 8);
#pragma unroll
                for (int mt = 0; mt < 2; mt++) MMA_BF16(acc[mt][nt], a[mt], b0, b1r);
            }
        }
    }

    // ---- all warps done with Asm/Bsm; overlay Cs and dump ----
    __syncthreads();
#pragma unroll
    for (int mt = 0; mt < 2; mt++) {
#pragma unroll
        for (int nt = 0; nt < 8; nt++) {
            int r = warp_m * 32 + mt * 16 + gr;
            int c = warp_n * 64 + nt * 8 + 2 * qg;
            Cs[(r    ) * C_STRIDE + c    ] = acc[mt][nt][0];
            Cs[(r    ) * C_STRIDE + c + 1] = acc[mt][nt][1];
            Cs[(r + 8) * C_STRIDE + c    ] = acc[mt][nt][2];
            Cs[(r + 8) * C_STRIDE + c + 1] = acc[mt][nt][3];
        }
    }
    __syncthreads();

    // ---- per-thread softmax epilogue ----
    {
        int p  = tid >> 6;
        int cb = tid & 63;
        int n_pt = pt0 + p;
#pragma unroll
        for (int cc = 0; cc < 4; cc++) {
            int c = cb + cc * 64;
            float tv = g_theta[(size_t)n_pt * C_DIM + c];
            float bb = b2[c];
            float df[KNN];
            float mx = -3.4e38f;
#pragma unroll
            for (int k = 0; k < KNN; k++) {
                int j = idxs[p * KNN + k];
                float ph = g_phi[(size_t)j * C_DIM + c];
                float pe = Cs[(p * KNN + k) * C_STRIDE + c] + bb;
                float v = pe * (tv - ph + 1.0f) * 0.0625f;
                df[k] = v;
                mx = fmaxf(mx, v);
            }
            float s = 0.0f;
#pragma unroll
            for (int k = 0; k < KNN; k++) { df[k] = __expf(df[k] - mx); s += df[k]; }
            float inv = 1.0f / s;
            float y = 0.0f;
#pragma unroll
            for (int k = 0; k < KNN; k++) {
                int j = idxs[p * KNN + k];
                y = fmaf(df[k] * inv, g_gf[(size_t)j * C_DIM + c], y);
            }
            g_y[(size_t)n_pt * C_DIM + c] = y;
        }
    }
}

// ---------------- launch ----------------------------------------------------
extern "C" void kernel_launch(void* const* d_in, const int* in_sizes, int n_in,
                              void* d_out, int out_size) {
    const float* coords  = (const float*)d_in[0];
    const float* feats   = (const float*)d_in[1];
    const float* theta_w = (const float*)d_in[2];
    const float* theta_b = (const float*)d_in[3];
    const float* phi_w   = (const float*)d_in[4];
    const float* phi_b   = (const float*)d_in[5];
    const float* g_w     = (const float*)d_in[6];
    const float* g_b     = (const float*)d_in[7];
    const float* pe1_w1  = (const float*)d_in[8];
    const float* pe1_b1  = (const float*)d_in[9];
    const float* pe1_w2  = (const float*)d_in[10];
    const float* pe1_b2  = (const float*)d_in[11];
    const float* W_w     = (const float*)d_in[12];
    const float* W_b     = (const float*)d_in[13];
    float* out = (float*)d_out;

    float *p_theta, *p_phi, *p_gf, *p_y;
    cudaGetSymbolAddress((void**)&p_theta, g_theta);
    cudaGetSymbolAddress((void**)&p_phi,   g_phi);
    cudaGetSymbolAddress((void**)&p_gf,    g_gf);
    cudaGetSymbolAddress((void**)&p_y,     g_y);

    cudaFuncSetAttribute(pe_attn3_kernel,
                         cudaFuncAttributeMaxDynamicSharedMemorySize, SMEM_TOTAL_PE);

    // grid KNN pipeline
    cell_zero_kernel<<<NCELLS / 256, 256>>>();
    cell_count_kernel<<<N_PTS / 256, 256>>>(coords);
    cell_scan_kernel<<<1, 512>>>();
    cell_scatter_kernel<<<N_PTS / 256, 256>>>(coords);
    knn_grid_kernel<<<N_PTS / 128, 128>>>(coords);

    w2_prep_kernel<<<C_DIM * C_DIM / 256, 256>>>(pe1_w2);

    dim3 gt(C_DIM / 64, N_PTS / 128);   // (4, 64)
    gemm3_tf32_kernel<<<gt, 256>>>(feats, theta_w, phi_w, g_w,
                                   theta_b, phi_b, g_b,
                                   p_theta, p_phi, p_gf);

    pe_attn3_kernel<<<N_PTS * KNN / 128, 512, SMEM_TOTAL_PE>>>(pe1_w1, pe1_b1, pe1_b2);

    gemm_tf32_resid_kernel<<<gt, 256>>>(p_y, W_w, W_b, feats, out);
}